// round 1
// baseline (speedup 1.0000x reference)
#include <cuda_runtime.h>

// Problem: x (16, 4096, 1024) fp32  ->  out[b][d] = sum_t x[b][t][d]   (16, 1024) fp32
// Pure HBM-streaming reduction. Two deterministic passes, no atomics.

#define BATCH   16
#define T_DIM   4096
#define D_DIM   1024
#define T_SPLIT 32                       // blocks along T per batch
#define T_PER   (T_DIM / T_SPLIT)        // 128 rows per block
#define D_VEC   (D_DIM / 4)              // 256 float4 per row  -> 256 threads/block

// Scratch for partial sums: [T_SPLIT][BATCH][D_DIM]  = 32*16*1024 floats = 2 MiB
__device__ float g_partial[T_SPLIT * BATCH * D_DIM];

__device__ __forceinline__ float4 ldcs4(const float4* p) {
    float4 v;
    asm volatile("ld.global.cs.v4.f32 {%0,%1,%2,%3}, [%4];"
                 : "=f"(v.x), "=f"(v.y), "=f"(v.z), "=f"(v.w) : "l"(p));
    return v;
}

__global__ void __launch_bounds__(D_VEC, 4) sum_pass1(const float* __restrict__ x) {
    const int b = blockIdx.x;        // batch
    const int s = blockIdx.y;        // T-slice
    const int dv = threadIdx.x;      // float4 index within D

    // base of this block's contiguous chunk: rows [s*T_PER, (s+1)*T_PER) of batch b
    const float4* base = reinterpret_cast<const float4*>(
        x + ((size_t)b * T_DIM + (size_t)s * T_PER) * D_DIM) + dv;
    const int rowStride = D_DIM / 4;   // 256 float4 between consecutive t rows

    float4 a0 = make_float4(0.f, 0.f, 0.f, 0.f);
    float4 a1 = a0, a2 = a0, a3 = a0;

    #pragma unroll 4
    for (int t = 0; t < T_PER; t += 4) {
        float4 v0 = ldcs4(base + (size_t)(t + 0) * rowStride);
        float4 v1 = ldcs4(base + (size_t)(t + 1) * rowStride);
        float4 v2 = ldcs4(base + (size_t)(t + 2) * rowStride);
        float4 v3 = ldcs4(base + (size_t)(t + 3) * rowStride);
        a0.x += v0.x; a0.y += v0.y; a0.z += v0.z; a0.w += v0.w;
        a1.x += v1.x; a1.y += v1.y; a1.z += v1.z; a1.w += v1.w;
        a2.x += v2.x; a2.y += v2.y; a2.z += v2.z; a2.w += v2.w;
        a3.x += v3.x; a3.y += v3.y; a3.z += v3.z; a3.w += v3.w;
    }

    float4 r;
    r.x = (a0.x + a1.x) + (a2.x + a3.x);
    r.y = (a0.y + a1.y) + (a2.y + a3.y);
    r.z = (a0.z + a1.z) + (a2.z + a3.z);
    r.w = (a0.w + a1.w) + (a2.w + a3.w);

    // layout [s][b][d] so pass-2 reads are coalesced over the fused (b,d) index
    float4* dst = reinterpret_cast<float4*>(
        g_partial + ((size_t)s * BATCH + b) * D_DIM) + dv;
    *dst = r;
}

__global__ void sum_pass2(float* __restrict__ out) {
    const int i = blockIdx.x * blockDim.x + threadIdx.x;   // 0 .. BATCH*D_DIM-1
    float acc = 0.f;
    #pragma unroll
    for (int s = 0; s < T_SPLIT; ++s)
        acc += g_partial[(size_t)s * (BATCH * D_DIM) + i];
    out[i] = acc;
}

extern "C" void kernel_launch(void* const* d_in, const int* in_sizes, int n_in,
                              void* d_out, int out_size) {
    const float* x = (const float*)d_in[0];
    float* out = (float*)d_out;

    dim3 grid1(BATCH, T_SPLIT);
    sum_pass1<<<grid1, D_VEC>>>(x);

    const int total = BATCH * D_DIM;            // 16384
    sum_pass2<<<total / 256, 256>>>(out);
    (void)in_sizes; (void)n_in; (void)out_size;
}